// round 3
// baseline (speedup 1.0000x reference)
#include <cuda_runtime.h>

#define NTOK 16384
#define NEXP 64
#define DIM  2048
#define KC   32
#define KPAIRS (KC / 2)        // 16
#define CHUNKS (DIM / KC)      // 64
#define TOKB 32
#define THREADS 128
#define XROW 36                // floats per X row (KC + 4 pad) = 144B, 16B-aligned
#define NBUF 3

typedef unsigned long long ull;

// W interleaved by k-pair: for expert e (sub=e>>3, r=e&7, j=r>>1, lane=r&1), k=2kp+w:
//   g_Wp[kp*128 + (j*8+sub)*4 + lane*2 + w] = W[e][k]
// => warp's 8 subs reading chunk j of kpair kp hit ONE contiguous 128B line.
__device__ float g_Wp[(DIM / 2) * 128];

// ---------- f32x2 helpers ----------
__device__ __forceinline__ void unpack2(ull v, float& lo, float& hi) {
    asm("mov.b64 {%0, %1}, %2;" : "=f"(lo), "=f"(hi) : "l"(v));
}
__device__ __forceinline__ ull fma2(ull a, ull b, ull c) {
    ull d;
    asm("fma.rn.f32x2 %0, %1, %2, %3;" : "=l"(d) : "l"(a), "l"(b), "l"(c));
    return d;
}
__device__ __forceinline__ void cpasync16(unsigned s, const void* g) {
    asm volatile("cp.async.cg.shared.global [%0], [%1], 16;" :: "r"(s), "l"(g));
}
__device__ __forceinline__ void cp_commit() {
    asm volatile("cp.async.commit_group;");
}

// ---------- kernel 1: interleave W ----------
__global__ void prep_W(const float* __restrict__ W) {
    int i = blockIdx.x * blockDim.x + threadIdx.x;
    if (i < DIM * NEXP) {
        int e = i >> 11;           // expert (row), k contiguous -> coalesced read
        int k = i & (DIM - 1);
        int kp = k >> 1, w = k & 1;
        int sub = e >> 3, r = e & 7, j = r >> 1, lane = r & 1;
        g_Wp[kp * 128 + (j * 8 + sub) * 4 + lane * 2 + w] = W[i];
    }
}

// ---------- kernel 2: fused GEMM + bias + top-2 + softmax ----------
__global__ __launch_bounds__(THREADS, 3)
void gate_kernel(const float* __restrict__ inp,
                 const float* __restrict__ bias,
                 float* __restrict__ out,
                 int out_size) {
    __shared__ __align__(16) float Wsm[NBUF][KPAIRS * 128];  // 3 x 8 KB
    __shared__ __align__(16) float Xsm[NBUF][TOKB * XROW];   // 3 x 4.5 KB

    const int tid = threadIdx.x;
    const int sub = tid & 7;          // expert group: experts 8*sub .. 8*sub+7
    const int tp  = tid >> 3;         // token pair 0..15 -> tokens 2tp, 2tp+1
    const int tokBase = blockIdx.x * TOKB;

    // staging geometry (per thread, per chunk):
    //   W: 64B contiguous (4 x cp.async.16)
    //   X: token = tid>>2, 32B segment = (tid&3)*32 (2 x cp.async.16)
    const int xTok  = tid >> 2;
    const int xPart = tid & 3;
    const float* xSrcBase = inp + (size_t)(tokBase + xTok) * DIM + xPart * 8;

    ull acc[2][8];
#pragma unroll
    for (int t = 0; t < 2; t++)
#pragma unroll
        for (int p = 0; p < 8; p++) acc[t][p] = 0ull;

    // ---- prologue: stage chunk 0 into buffer 0 ----
    {
        unsigned wd = (unsigned)__cvta_generic_to_shared(&Wsm[0][0]) + tid * 64;
        const char* ws = (const char*)(g_Wp) + tid * 64;
#pragma unroll
        for (int i = 0; i < 4; i++) cpasync16(wd + i * 16, ws + i * 16);
        unsigned xd = (unsigned)__cvta_generic_to_shared(&Xsm[0][xTok * XROW]) + xPart * 32;
        cpasync16(xd, xSrcBase);
        cpasync16(xd + 16, xSrcBase + 4);
        cp_commit();
    }

    for (int c = 0; c < CHUNKS; c++) {
        const int b = c % NBUF;
        if (c + 1 < CHUNKS) {
            const int nb = (c + 1) % NBUF;
            unsigned wd = (unsigned)__cvta_generic_to_shared(&Wsm[nb][0]) + tid * 64;
            const char* ws = (const char*)(g_Wp + (size_t)(c + 1) * KPAIRS * 128) + tid * 64;
#pragma unroll
            for (int i = 0; i < 4; i++) cpasync16(wd + i * 16, ws + i * 16);
            unsigned xd = (unsigned)__cvta_generic_to_shared(&Xsm[nb][xTok * XROW]) + xPart * 32;
            const float* xs = xSrcBase + (c + 1) * KC;
            cpasync16(xd, xs);
            cpasync16(xd + 16, xs + 4);
            cp_commit();
            asm volatile("cp.async.wait_group 1;");
        } else {
            asm volatile("cp.async.wait_group 0;");
        }
        __syncthreads();   // single barrier per chunk (triple buffer makes WAR safe)

        const float* wb = &Wsm[b][sub * 4];
        const ull* x0 = (const ull*)&Xsm[b][(2 * tp) * XROW];
        const ull* x1 = (const ull*)&Xsm[b][(2 * tp + 1) * XROW];
#pragma unroll
        for (int kp = 0; kp < KPAIRS; kp++) {
            ulonglong2 w0 = *(const ulonglong2*)(wb + kp * 128);        // experts e0+0, e0+1
            ulonglong2 w1 = *(const ulonglong2*)(wb + kp * 128 + 32);   // experts e0+2, e0+3
            ulonglong2 w2 = *(const ulonglong2*)(wb + kp * 128 + 64);   // experts e0+4, e0+5
            ulonglong2 w3 = *(const ulonglong2*)(wb + kp * 128 + 96);   // experts e0+6, e0+7
            ull xv0 = x0[kp];
            ull xv1 = x1[kp];
            acc[0][0] = fma2(w0.x, xv0, acc[0][0]);
            acc[0][1] = fma2(w0.y, xv0, acc[0][1]);
            acc[0][2] = fma2(w1.x, xv0, acc[0][2]);
            acc[0][3] = fma2(w1.y, xv0, acc[0][3]);
            acc[0][4] = fma2(w2.x, xv0, acc[0][4]);
            acc[0][5] = fma2(w2.y, xv0, acc[0][5]);
            acc[0][6] = fma2(w3.x, xv0, acc[0][6]);
            acc[0][7] = fma2(w3.y, xv0, acc[0][7]);
            acc[1][0] = fma2(w0.x, xv1, acc[1][0]);
            acc[1][1] = fma2(w0.y, xv1, acc[1][1]);
            acc[1][2] = fma2(w1.x, xv1, acc[1][2]);
            acc[1][3] = fma2(w1.y, xv1, acc[1][3]);
            acc[1][4] = fma2(w2.x, xv1, acc[1][4]);
            acc[1][5] = fma2(w2.y, xv1, acc[1][5]);
            acc[1][6] = fma2(w3.x, xv1, acc[1][6]);
            acc[1][7] = fma2(w3.y, xv1, acc[1][7]);
        }
    }

    // ---- fused epilogue: reduce pair, +bias, top-2, softmax ----
    const int half = out_size >> 1;
    const int e0 = sub * 8;

#pragma unroll
    for (int t = 0; t < 2; t++) {
        float v0 = -3.4e38f, v1 = -3.4e38f;
        int   i0 = -1,       i1 = -1;
#pragma unroll
        for (int p = 0; p < 8; p++) {
            float lo, hi;
            unpack2(acc[t][p], lo, hi);
            float f = lo + hi + bias[e0 + p];
            int e = e0 + p;
            if (f > v0)      { v1 = v0; i1 = i0; v0 = f; i0 = e; }
            else if (f > v1) { v1 = f;  i1 = e; }
        }
        // butterfly merge over the 8 sub-lanes of this token
#pragma unroll
        for (int ofs = 1; ofs < 8; ofs <<= 1) {
            float u0 = __shfl_xor_sync(0xFFFFFFFFu, v0, ofs);
            float u1 = __shfl_xor_sync(0xFFFFFFFFu, v1, ofs);
            int   j0 = __shfl_xor_sync(0xFFFFFFFFu, i0, ofs);
            int   j1 = __shfl_xor_sync(0xFFFFFFFFu, i1, ofs);
            bool afirst = (v0 > u0) || (v0 == u0 && i0 < j0);
            float nv0, nv1; int ni0, ni1;
            if (afirst) {
                nv0 = v0; ni0 = i0;
                bool s = (u0 > v1) || (u0 == v1 && j0 < i1);
                nv1 = s ? u0 : v1; ni1 = s ? j0 : i1;
            } else {
                nv0 = u0; ni0 = j0;
                bool s = (v0 > u1) || (v0 == u1 && i0 < j1);
                nv1 = s ? v0 : u1; ni1 = s ? i0 : j1;
            }
            v0 = nv0; v1 = nv1; i0 = ni0; i1 = ni1;
        }
        if (sub == 0) {
            int tok = tokBase + 2 * tp + t;
            float e  = expf(v1 - v0);
            float s0 = 1.0f / (1.0f + e);
            float s1 = e * s0;
            out[tok * 2 + 0] = (float)i0;
            out[tok * 2 + 1] = (float)i1;
            out[half + tok * 2 + 0] = s0;
            out[half + tok * 2 + 1] = s1;
        }
    }
}

extern "C" void kernel_launch(void* const* d_in, const int* in_sizes, int n_in,
                              void* d_out, int out_size) {
    const float* inp  = (const float*)d_in[0];   // [16384, 2048]
    const float* W    = (const float*)d_in[1];   // [64, 2048]
    const float* bias = (const float*)d_in[2];   // [64]
    float* out = (float*)d_out;

    prep_W<<<(DIM * NEXP + 255) / 256, 256>>>(W);
    gate_kernel<<<NTOK / TOKB, THREADS>>>(inp, bias, out, out_size);
}

// round 4
// speedup vs baseline: 1.2507x; 1.2507x over previous
#include <cuda_runtime.h>

#define NTOK 16384
#define NEXP 64
#define DIM  2048
#define KC   32
#define KPAIRS (KC / 2)        // 16
#define CHUNKS (DIM / KC)      // 64
#define TOKB 64
#define THREADS 128
#define XROWF 36               // floats per X token row (32 + 4 pad) = 144B, 16B-aligned
#define XROWU (XROWF / 2)      // 18 ull
#define NBUF 3

typedef unsigned long long ull;

// W packed as f32x2-per-kpair ull, laid out so one warp LDS.64 = 64B contiguous:
//   ull index u = kp*64 + p*8 + sub  holds {W[8*sub+p][2kp], W[8*sub+p][2kp+1]}
__device__ ull g_Wp[(DIM / 2) * 64];

// ---------- f32x2 helpers ----------
__device__ __forceinline__ void unpack2(ull v, float& lo, float& hi) {
    asm("mov.b64 {%0, %1}, %2;" : "=f"(lo), "=f"(hi) : "l"(v));
}
__device__ __forceinline__ ull fma2(ull a, ull b, ull c) {
    ull d;
    asm("fma.rn.f32x2 %0, %1, %2, %3;" : "=l"(d) : "l"(a), "l"(b), "l"(c));
    return d;
}
__device__ __forceinline__ void cpasync16(unsigned s, const void* g) {
    asm volatile("cp.async.cg.shared.global [%0], [%1], 16;" :: "r"(s), "l"(g));
}
__device__ __forceinline__ void cp_commit() {
    asm volatile("cp.async.commit_group;");
}

// ---------- kernel 1: pack + permute W ----------
__global__ void prep_W(const float* __restrict__ W) {
    int i = blockIdx.x * blockDim.x + threadIdx.x;
    if (i < DIM * NEXP) {
        int e = i >> 11;            // expert row (k contiguous -> coalesced read)
        int k = i & (DIM - 1);
        int kp = k >> 1, w = k & 1;
        int sub = e >> 3, p = e & 7;
        ((float*)g_Wp)[(kp * 64 + p * 8 + sub) * 2 + w] = W[i];
    }
}

// ---------- kernel 2: fused GEMM + bias + top-2 + softmax ----------
__global__ __launch_bounds__(THREADS)
void gate_kernel(const float* __restrict__ inp,
                 const float* __restrict__ bias,
                 float* __restrict__ out,
                 int out_size) {
    __shared__ __align__(16) ull   Wsm[NBUF][KPAIRS * 64];    // 3 x 8 KB
    __shared__ __align__(16) float Xsm[NBUF][TOKB * XROWF];   // 3 x 9 KB

    const int tid = threadIdx.x;
    const int sub = tid & 7;          // expert group: experts 8*sub .. 8*sub+7
    const int tp  = tid >> 3;         // 0..15; tokens tp, tp+16, tp+32, tp+48
    const int tokBase = blockIdx.x * TOKB;

    // staging geometry: W 64B/thread contiguous; X token=tid>>1, half=(tid&1)*64B
    const int xTok  = tid >> 1;
    const int xHalf = tid & 1;
    const float* xSrcBase = inp + (size_t)(tokBase + xTok) * DIM + xHalf * 16;

    ull acc[4][8];
#pragma unroll
    for (int j = 0; j < 4; j++)
#pragma unroll
        for (int p = 0; p < 8; p++) acc[j][p] = 0ull;

    const unsigned wD0 = (unsigned)__cvta_generic_to_shared(&Wsm[0][0]);
    const unsigned xD0 = (unsigned)__cvta_generic_to_shared(&Xsm[0][0]);
    const unsigned wBufSz = KPAIRS * 64 * 8;   // 8192
    const unsigned xBufSz = TOKB * XROWF * 4;  // 9216

    // stage chunk c into buffer b
    auto stage = [&](int c, int b) {
        unsigned wd = wD0 + b * wBufSz + tid * 64;
        const char* ws = (const char*)(g_Wp + (size_t)c * KPAIRS * 64) + tid * 64;
#pragma unroll
        for (int i = 0; i < 4; i++) cpasync16(wd + i * 16, ws + i * 16);
        unsigned xd = xD0 + b * xBufSz + (xTok * XROWF + xHalf * 16) * 4;
        const float* xs = xSrcBase + c * KC;
#pragma unroll
        for (int i = 0; i < 4; i++) cpasync16(xd + i * 16, xs + i * 4);
    };

    // prologue: chunks 0 and 1 in flight
    stage(0, 0); cp_commit();
    stage(1, 1); cp_commit();

    for (int c = 0; c < CHUNKS; c++) {
        const int b = c % NBUF;
        if (c + 2 < CHUNKS) stage(c + 2, (c + 2) % NBUF);
        cp_commit();                                // (possibly empty group)
        asm volatile("cp.async.wait_group 2;");     // chunk c's group complete
        __syncthreads();                            // all threads' stages visible

        const ull* wb = &Wsm[b][sub];
        const ull* xb = (const ull*)&Xsm[b][0];
#pragma unroll
        for (int kp = 0; kp < KPAIRS; kp++) {
            ull w0 = wb[kp * 64 + 0];
            ull w1 = wb[kp * 64 + 8];
            ull w2 = wb[kp * 64 + 16];
            ull w3 = wb[kp * 64 + 24];
            ull w4 = wb[kp * 64 + 32];
            ull w5 = wb[kp * 64 + 40];
            ull w6 = wb[kp * 64 + 48];
            ull w7 = wb[kp * 64 + 56];
            ull x0 = xb[(tp)      * XROWU + kp];
            ull x1 = xb[(tp + 16) * XROWU + kp];
            ull x2 = xb[(tp + 32) * XROWU + kp];
            ull x3 = xb[(tp + 48) * XROWU + kp];
            acc[0][0] = fma2(w0, x0, acc[0][0]);
            acc[0][1] = fma2(w1, x0, acc[0][1]);
            acc[0][2] = fma2(w2, x0, acc[0][2]);
            acc[0][3] = fma2(w3, x0, acc[0][3]);
            acc[0][4] = fma2(w4, x0, acc[0][4]);
            acc[0][5] = fma2(w5, x0, acc[0][5]);
            acc[0][6] = fma2(w6, x0, acc[0][6]);
            acc[0][7] = fma2(w7, x0, acc[0][7]);
            acc[1][0] = fma2(w0, x1, acc[1][0]);
            acc[1][1] = fma2(w1, x1, acc[1][1]);
            acc[1][2] = fma2(w2, x1, acc[1][2]);
            acc[1][3] = fma2(w3, x1, acc[1][3]);
            acc[1][4] = fma2(w4, x1, acc[1][4]);
            acc[1][5] = fma2(w5, x1, acc[1][5]);
            acc[1][6] = fma2(w6, x1, acc[1][6]);
            acc[1][7] = fma2(w7, x1, acc[1][7]);
            acc[2][0] = fma2(w0, x2, acc[2][0]);
            acc[2][1] = fma2(w1, x2, acc[2][1]);
            acc[2][2] = fma2(w2, x2, acc[2][2]);
            acc[2][3] = fma2(w3, x2, acc[2][3]);
            acc[2][4] = fma2(w4, x2, acc[2][4]);
            acc[2][5] = fma2(w5, x2, acc[2][5]);
            acc[2][6] = fma2(w6, x2, acc[2][6]);
            acc[2][7] = fma2(w7, x2, acc[2][7]);
            acc[3][0] = fma2(w0, x3, acc[3][0]);
            acc[3][1] = fma2(w1, x3, acc[3][1]);
            acc[3][2] = fma2(w2, x3, acc[3][2]);
            acc[3][3] = fma2(w3, x3, acc[3][3]);
            acc[3][4] = fma2(w4, x3, acc[3][4]);
            acc[3][5] = fma2(w5, x3, acc[3][5]);
            acc[3][6] = fma2(w6, x3, acc[3][6]);
            acc[3][7] = fma2(w7, x3, acc[3][7]);
        }
        __syncthreads();   // WAR: next stages may overwrite buffer (c-1)%3
    }

    // ---- fused epilogue: reduce pair halves, +bias, top-2, softmax ----
    const int half = out_size >> 1;
    const int e0 = sub * 8;
    float bv[8];
#pragma unroll
    for (int p = 0; p < 8; p++) bv[p] = bias[e0 + p];

#pragma unroll
    for (int j = 0; j < 4; j++) {
        float v0 = -3.4e38f, v1 = -3.4e38f;
        int   i0 = -1,       i1 = -1;
#pragma unroll
        for (int p = 0; p < 8; p++) {
            float lo, hi;
            unpack2(acc[j][p], lo, hi);
            float f = lo + hi + bv[p];
            int e = e0 + p;
            if (f > v0)      { v1 = v0; i1 = i0; v0 = f; i0 = e; }
            else if (f > v1) { v1 = f;  i1 = e; }
        }
        // butterfly merge over the 8 sub-lanes owning this token
#pragma unroll
        for (int ofs = 1; ofs < 8; ofs <<= 1) {
            float u0 = __shfl_xor_sync(0xFFFFFFFFu, v0, ofs);
            float u1 = __shfl_xor_sync(0xFFFFFFFFu, v1, ofs);
            int   j0 = __shfl_xor_sync(0xFFFFFFFFu, i0, ofs);
            int   j1 = __shfl_xor_sync(0xFFFFFFFFu, i1, ofs);
            bool afirst = (v0 > u0) || (v0 == u0 && i0 < j0);
            float nv0, nv1; int ni0, ni1;
            if (afirst) {
                nv0 = v0; ni0 = i0;
                bool s = (u0 > v1) || (u0 == v1 && j0 < i1);
                nv1 = s ? u0 : v1; ni1 = s ? j0 : i1;
            } else {
                nv0 = u0; ni0 = j0;
                bool s = (v0 > u1) || (v0 == u1 && i0 < j1);
                nv1 = s ? v0 : u1; ni1 = s ? i0 : j1;
            }
            v0 = nv0; v1 = nv1; i0 = ni0; i1 = ni1;
        }
        if (sub == 0) {
            int tok = tokBase + tp + 16 * j;
            float e  = expf(v1 - v0);
            float s0 = 1.0f / (1.0f + e);
            float s1 = e * s0;
            out[tok * 2 + 0] = (float)i0;
            out[tok * 2 + 1] = (float)i1;
            out[half + tok * 2 + 0] = s0;
            out[half + tok * 2 + 1] = s1;
        }
    }
}

extern "C" void kernel_launch(void* const* d_in, const int* in_sizes, int n_in,
                              void* d_out, int out_size) {
    const float* inp  = (const float*)d_in[0];   // [16384, 2048]
    const float* W    = (const float*)d_in[1];   // [64, 2048]
    const float* bias = (const float*)d_in[2];   // [64]
    float* out = (float*)d_out;

    prep_W<<<(DIM * NEXP + 255) / 256, 256>>>(W);
    gate_kernel<<<NTOK / TOKB, THREADS>>>(inp, bias, out, out_size);
}